// round 17
// baseline (speedup 1.0000x reference)
#include <cuda_runtime.h>
#include <cuda_fp16.h>
#include <stdint.h>

#define NB 2
#define CD 256
#define LL 4096
#define NH 4
#define DKH 64

static constexpr float LOG2E = 1.4426950408889634f;

__device__ float  g_x  [NB * LL * CD];        // residual: [b][l][c] fp32
__device__ __half g_xh [NB * LL * CD];        // x hi (fp16)
__device__ __half g_xl [NB * LL * CD];        // x lo (fp16)
__device__ __half g_v  [NB * NH * LL * DKH];  // q/k/v heads (fp16)
__device__ __half g_ath[NB * LL * CD];        // attn out (fp16)
__device__ float  g_y  [NB * LL * CD];        // fc+residual
__device__ __half g_wqh[CD * CD];             // w_qkv hi/lo
__device__ __half g_wql[CD * CD];
__device__ __half g_fwh[CD * CD];             // fc_w (fp16)
__device__ float  g_norm[NB * NH * LL];       // per-row |q|
__device__ int    g_gmax[NB * NH];            // per-(b,h) max |q| (int bits)
__device__ float  g_part[2 * NB * NH * LL * DKH];  // split-KV O partials (fp32)
__device__ float  g_lp  [2 * NB * NH * LL];        // split-KV l partials

// ------------------------- helpers -------------------------
__device__ __forceinline__ uint32_t smem_u32(const void* p) {
    uint32_t a;
    asm("{ .reg .u64 t; cvta.to.shared.u64 t, %1; cvt.u32.u64 %0, t; }"
        : "=r"(a) : "l"(p));
    return a;
}
__device__ __forceinline__ uint32_t SWZ(uint32_t o) {
    return o ^ ((o >> 3) & 0x70);
}
__device__ __forceinline__ void ldsm4(uint32_t* r, uint32_t a) {
    asm volatile("ldmatrix.sync.aligned.m8n8.x4.shared.b16 {%0,%1,%2,%3}, [%4];"
                 : "=r"(r[0]), "=r"(r[1]), "=r"(r[2]), "=r"(r[3]) : "r"(a));
}
__device__ __forceinline__ void ldsm4t(uint32_t* r, uint32_t a) {
    asm volatile("ldmatrix.sync.aligned.m8n8.x4.trans.shared.b16 {%0,%1,%2,%3}, [%4];"
                 : "=r"(r[0]), "=r"(r[1]), "=r"(r[2]), "=r"(r[3]) : "r"(a));
}
__device__ __forceinline__ void mma_f16(float* d, const uint32_t* a,
                                        uint32_t b0, uint32_t b1) {
    asm volatile(
        "mma.sync.aligned.m16n8k16.row.col.f32.f16.f16.f32 "
        "{%0,%1,%2,%3}, {%4,%5,%6,%7}, {%8,%9}, {%0,%1,%2,%3};"
        : "+f"(d[0]), "+f"(d[1]), "+f"(d[2]), "+f"(d[3])
        : "r"(a[0]), "r"(a[1]), "r"(a[2]), "r"(a[3]), "r"(b0), "r"(b1));
}
__device__ __forceinline__ void mma_f16s(float* d, uint32_t a0, uint32_t a1,
                                         uint32_t a2, uint32_t a3,
                                         uint32_t b0, uint32_t b1) {
    asm volatile(
        "mma.sync.aligned.m16n8k16.row.col.f32.f16.f16.f32 "
        "{%0,%1,%2,%3}, {%4,%5,%6,%7}, {%8,%9}, {%0,%1,%2,%3};"
        : "+f"(d[0]), "+f"(d[1]), "+f"(d[2]), "+f"(d[3])
        : "r"(a0), "r"(a1), "r"(a2), "r"(a3), "r"(b0), "r"(b1));
}
__device__ __forceinline__ float ex2f(float x) {
    float y;
    asm("ex2.approx.ftz.f32 %0, %1;" : "=f"(y) : "f"(x));
    return y;
}
__device__ __forceinline__ uint32_t pk_h2(float a, float b) {
    __half2 h = __floats2half2_rn(a, b);
    return *(uint32_t*)&h;
}
__device__ __forceinline__ void cpa16(uint32_t s, const void* g) {
    asm volatile("cp.async.cg.shared.global [%0], [%1], 16;" :: "r"(s), "l"(g));
}
__device__ __forceinline__ void cpa_commit() {
    asm volatile("cp.async.commit_group;" ::: "memory");
}
template <int N>
__device__ __forceinline__ void cpa_wait() {
    asm volatile("cp.async.wait_group %0;" :: "n"(N) : "memory");
}

// ---------------------------------------------------------------------------
// Kernel 0a: transpose input -> g_x (fp32) + g_xh/g_xl (fp16 hi/lo)
// ---------------------------------------------------------------------------
__global__ __launch_bounds__(256) void k_prep(const float* __restrict__ qin) {
    __shared__ float T[64][65];
    const int bt = blockIdx.z, c0 = blockIdx.y * 64, l0 = blockIdx.x * 64;
    const int tid = threadIdx.x;
    #pragma unroll
    for (int i = 0; i < 16; i++) {
        int idx = tid + i * 256;
        int ci = idx >> 6, lj = idx & 63;
        T[ci][lj] = qin[(size_t)bt * CD * LL + (size_t)(c0 + ci) * LL + l0 + lj];
    }
    __syncthreads();
    #pragma unroll
    for (int i = 0; i < 16; i++) {
        int idx = tid + i * 256;
        int li = idx >> 6, cj = idx & 63;
        float v = T[cj][li];
        size_t o = (size_t)(bt * LL + l0 + li) * CD + c0 + cj;
        g_x[o] = v;
        __half h = __float2half_rn(v);
        g_xh[o] = h;
        g_xl[o] = __float2half_rn(v - __half2float(h));
    }
}

// ---------------------------------------------------------------------------
// Kernel 0b: weights -> fp16 (wq hi/lo, fc single) + reset gmax
// ---------------------------------------------------------------------------
__global__ __launch_bounds__(256) void k_prep_w(const float* __restrict__ wq,
                                                const float* __restrict__ fw) {
    int idx = blockIdx.x * 256 + threadIdx.x;   // 65536 total
    if (idx < NB * NH) g_gmax[idx] = 0;
    float v = wq[idx];
    __half h = __float2half_rn(v);
    g_wqh[idx] = h;
    g_wql[idx] = __float2half_rn(v - __half2float(h));
    g_fwh[idx] = __float2half_rn(fw[idx]);
}

// ---------------------------------------------------------------------------
// qkv GEMM mainloop: M=128 x N=64 x K=256, fp16 hi/lo 3-MMA, pure cp.async.
// ---------------------------------------------------------------------------
__device__ __forceinline__ void gemm_ml(const char* gah, const char* gal,
                                        const char* gbh, const char* gbl,
                                        uint32_t base, int tid, int wid,
                                        uint32_t laneRow, uint32_t laneCol,
                                        float (&acc)[8][4]) {
    auto pref = [&](int kc) {
        uint32_t st = base + (uint32_t)(kc & 1) * 49152u;
        #pragma unroll
        for (int i = 0; i < 4; i++) {
            int idx = tid + i * 256;
            int r = idx >> 3, c8 = idx & 7;
            uint32_t so = SWZ(r * 128 + c8 * 16);
            size_t go = (size_t)r * 512 + (size_t)kc * 128 + c8 * 16;
            cpa16(st + so, gah + go);
            cpa16(st + 16384 + so, gal + go);
        }
        #pragma unroll
        for (int i = 0; i < 2; i++) {
            int idx = tid + i * 256;
            int r = idx >> 3, c8 = idx & 7;
            uint32_t so = SWZ(r * 128 + c8 * 16);
            size_t go = (size_t)r * 512 + (size_t)kc * 128 + c8 * 16;
            cpa16(st + 32768 + so, gbh + go);
            cpa16(st + 40960 + so, gbl + go);
        }
    };
    pref(0); cpa_commit();
    pref(1); cpa_commit();
    #pragma unroll
    for (int kc = 0; kc < 4; kc++) {
        if (kc < 3) cpa_wait<1>(); else cpa_wait<0>();
        __syncthreads();
        uint32_t sb = base + (uint32_t)(kc & 1) * 49152u;
        #pragma unroll
        for (int s = 0; s < 4; s++) {
            uint32_t ah[4], al[4];
            uint32_t offA = SWZ((wid * 16 + laneRow) * 128 + s * 32 + laneCol);
            ldsm4(ah, sb + offA);
            ldsm4(al, sb + 16384 + offA);
            #pragma unroll
            for (int nf = 0; nf < 4; nf++) {
                uint32_t offB = SWZ((nf * 16 + laneRow) * 128 + s * 32 + laneCol);
                uint32_t b4[4], c4[4];
                ldsm4(b4, sb + 32768 + offB);
                ldsm4(c4, sb + 40960 + offB);
                mma_f16(acc[2 * nf],     ah, b4[0], b4[2]);
                mma_f16(acc[2 * nf],     al, b4[0], b4[2]);
                mma_f16(acc[2 * nf],     ah, c4[0], c4[2]);
                mma_f16(acc[2 * nf + 1], ah, b4[1], b4[3]);
                mma_f16(acc[2 * nf + 1], al, b4[1], b4[3]);
                mma_f16(acc[2 * nf + 1], ah, c4[1], c4[3]);
            }
        }
        __syncthreads();
        if (kc + 2 < 4) { pref(kc + 2); cpa_commit(); }
    }
}

// ---------------------------------------------------------------------------
// Kernel 1: QKV projection (HMMA) -> g_v fp16 + row norms + per-(b,h) max
// ---------------------------------------------------------------------------
__global__ __launch_bounds__(256, 2) void k_qkv_mma() {
    extern __shared__ char smg[];
    const uint32_t base = smem_u32(smg);
    const int tid = threadIdx.x, lane = tid & 31, wid = tid >> 5;
    const int m0 = blockIdx.x * 128;
    const int h = blockIdx.y, bt = blockIdx.z, bh = bt * NH + h;
    const uint32_t laneRow = lane & 15;
    const uint32_t laneCol = ((lane >> 4) & 1) * 16;

    float acc[8][4] = {};
    gemm_ml((const char*)(g_xh + (size_t)(bt * LL + m0) * CD),
            (const char*)(g_xl + (size_t)(bt * LL + m0) * CD),
            (const char*)(g_wqh + (size_t)h * 64 * CD),
            (const char*)(g_wql + (size_t)h * 64 * CD),
            base, tid, wid, laneRow, laneCol, acc);

    __half* gv = g_v + (size_t)bh * LL * DKH;
    const int r = m0 + wid * 16 + (lane >> 2);
    const int cb = (lane & 3) * 2;
    float s0 = 0.f, s1 = 0.f;
    #pragma unroll
    for (int f = 0; f < 8; f++) {
        int c = f * 8 + cb;
        *(uint32_t*)&gv[(size_t)r * DKH + c] = pk_h2(acc[f][0], acc[f][1]);
        *(uint32_t*)&gv[(size_t)(r + 8) * DKH + c] = pk_h2(acc[f][2], acc[f][3]);
        s0 += acc[f][0] * acc[f][0] + acc[f][1] * acc[f][1];
        s1 += acc[f][2] * acc[f][2] + acc[f][3] * acc[f][3];
    }
    s0 += __shfl_xor_sync(0xffffffffu, s0, 1);
    s0 += __shfl_xor_sync(0xffffffffu, s0, 2);
    s1 += __shfl_xor_sync(0xffffffffu, s1, 1);
    s1 += __shfl_xor_sync(0xffffffffu, s1, 2);
    if ((lane & 3) == 0) {
        float n0 = sqrtf(s0), n1 = sqrtf(s1);
        g_norm[(size_t)bh * LL + r] = n0;
        g_norm[(size_t)bh * LL + r + 8] = n1;
        atomicMax(&g_gmax[bh], __float_as_int(fmaxf(n0, n1)));
    }
}

// ---------------------------------------------------------------------------
// Kernel 2: HMMA flash attention, split-KV x2. Fixed per-row exp shift
// (Q==K Cauchy-Schwarz) => partials over disjoint key ranges are additive.
// 128 threads / 4 warps; warp owns 32 q-rows (2 m-frags); CTA = 128 rows,
// 2048 keys (NT=16). Quarter-tile softmax chunks cap regs ~170 -> 3 CTAs/SM.
// Grid 512 CTAs. smem: 2-stage KV ring + 16KB Q = 48KB.
// Epilogue: UNNORMALIZED fp32 O partials + l partials.
// ---------------------------------------------------------------------------
__device__ __forceinline__ void prefetch_kv(uint32_t buf, const char* g, int tid) {
    #pragma unroll
    for (int i = 0; i < 8; i++) {
        int c = tid + i * 128;
        int n = c >> 3, c8 = c & 7;
        uint32_t go = n * 128 + c8 * 16;
        cpa16(buf + SWZ(go), g + go);
    }
}

__global__ __launch_bounds__(128, 3) void k_attn_mma() {
    extern __shared__ char sm[];
    const uint32_t base = smem_u32(sm);

    const int tid = threadIdx.x;
    const int lane = tid & 31;
    const int wid = tid >> 5;
    const int bh = blockIdx.y;
    const int m0 = blockIdx.x * 128;
    const int split = blockIdx.z;

    const char* gvb = (const char*)(g_v + (size_t)bh * LL * DKH);
    const char* gkb = gvb + (size_t)split * (LL / 2) * DKH * 2;  // key half

    const uint32_t laneRow = lane & 15;
    const uint32_t laneCol = ((lane >> 4) & 1) * 16;

    const uint32_t Qb = base + 32768;   // 16KB Q staging after 2x16KB ring

    #pragma unroll
    for (int i = 0; i < 8; i++) {
        int c = tid + i * 128;
        int n = c >> 3, c8 = c & 7;
        cpa16(Qb + SWZ(n * 128 + c8 * 16), gvb + (m0 + n) * 128 + c8 * 16);
    }
    cpa_commit();
    prefetch_kv(base, gkb, tid);
    cpa_commit();

    cpa_wait<1>();
    __syncthreads();

    uint32_t qh[2][4][4];
    #pragma unroll
    for (int mi = 0; mi < 2; mi++) {
        uint32_t rowb = (wid * 32 + mi * 16 + laneRow) * 128;
        #pragma unroll
        for (int c = 0; c < 4; c++)
            ldsm4(qh[mi][c], Qb + SWZ(rowb + c * 32 + laneCol));
    }

    const float c1 = LOG2E * 0.125f;
    const int rbase = m0 + wid * 32 + (lane >> 2);
    const float gmax = __int_as_float(g_gmax[bh]);
    float mc[2][2];
    #pragma unroll
    for (int mi = 0; mi < 2; mi++) {
        mc[mi][0] = g_norm[(size_t)bh * LL + rbase + mi * 16] * gmax * c1;
        mc[mi][1] = g_norm[(size_t)bh * LL + rbase + mi * 16 + 8] * gmax * c1;
    }

    float o[2][8][4] = {};
    float l[2][2] = {};

    const int NT = LL / 256;   // 16 tiles of 128 keys (half the sequence)
    for (int t = 0; t < NT; t++) {
        const uint32_t KVb = base + (uint32_t)(t & 1) * 16384;

        if (t + 1 < NT) {
            prefetch_kv(base + (uint32_t)((t + 1) & 1) * 16384,
                        gkb + (size_t)(t + 1) * 16384, tid);
            cpa_commit();
            cpa_wait<1>();
        } else {
            cpa_wait<0>();
        }
        __syncthreads();

        #pragma unroll
        for (int qt = 0; qt < 4; qt++) {
            const int nb = qt * 32;

            float s[2][4][4];
            #pragma unroll
            for (int mi = 0; mi < 2; mi++)
                #pragma unroll
                for (int j = 0; j < 4; j++)
                    #pragma unroll
                    for (int k = 0; k < 4; k++) s[mi][j][k] = 0.f;

            #pragma unroll
            for (int jp = 0; jp < 2; jp++) {
                #pragma unroll
                for (int c = 0; c < 4; c++) {
                    uint32_t off = SWZ((nb + jp * 16 + laneRow) * 128 +
                                       c * 32 + laneCol);
                    uint32_t bv[4];
                    ldsm4(bv, KVb + off);
                    mma_f16(s[0][2 * jp],     qh[0][c], bv[0], bv[2]);
                    mma_f16(s[0][2 * jp + 1], qh[0][c], bv[1], bv[3]);
                    mma_f16(s[1][2 * jp],     qh[1][c], bv[0], bv[2]);
                    mma_f16(s[1][2 * jp + 1], qh[1][c], bv[1], bv[3]);
                }
            }

            uint32_t p[2][4][2];
            #pragma unroll
            for (int mi = 0; mi < 2; mi++) {
                #pragma unroll
                for (int j = 0; j < 4; j++) {
                    float e0 = ex2f(fmaf(s[mi][j][0], c1, -mc[mi][0]));
                    float e1 = ex2f(fmaf(s[mi][j][1], c1, -mc[mi][0]));
                    float e2 = ex2f(fmaf(s[mi][j][2], c1, -mc[mi][1]));
                    float e3 = ex2f(fmaf(s[mi][j][3], c1, -mc[mi][1]));
                    l[mi][0] += e0 + e1;
                    l[mi][1] += e2 + e3;
                    p[mi][j][0] = pk_h2(e0, e1);
                    p[mi][j][1] = pk_h2(e2, e3);
                }
            }

            #pragma unroll
            for (int c = 0; c < 2; c++) {
                #pragma unroll
                for (int vp = 0; vp < 4; vp++) {
                    uint32_t off = SWZ((nb + c * 16 + laneRow) * 128 +
                                       vp * 32 + laneCol);
                    uint32_t bv[4];
                    ldsm4t(bv, KVb + off);
                    mma_f16s(o[0][2 * vp], p[0][2 * c][0], p[0][2 * c][1],
                             p[0][2 * c + 1][0], p[0][2 * c + 1][1],
                             bv[0], bv[1]);
                    mma_f16s(o[0][2 * vp + 1], p[0][2 * c][0], p[0][2 * c][1],
                             p[0][2 * c + 1][0], p[0][2 * c + 1][1],
                             bv[2], bv[3]);
                    mma_f16s(o[1][2 * vp], p[1][2 * c][0], p[1][2 * c][1],
                             p[1][2 * c + 1][0], p[1][2 * c + 1][1],
                             bv[0], bv[1]);
                    mma_f16s(o[1][2 * vp + 1], p[1][2 * c][0], p[1][2 * c][1],
                             p[1][2 * c + 1][0], p[1][2 * c + 1][1],
                             bv[2], bv[3]);
                }
            }
        }
        __syncthreads();
    }

    // ---- epilogue: write UNNORMALIZED partials ----
    #pragma unroll
    for (int mi = 0; mi < 2; mi++) {
        #pragma unroll
        for (int hsel = 0; hsel < 2; hsel++) {
            l[mi][hsel] += __shfl_xor_sync(0xffffffffu, l[mi][hsel], 1);
            l[mi][hsel] += __shfl_xor_sync(0xffffffffu, l[mi][hsel], 2);
        }
    }
    float* gp = g_part + ((size_t)split * NB * NH + bh) * LL * DKH;
    float* glp = g_lp + ((size_t)split * NB * NH + bh) * LL;
    const int cb = (lane & 3) * 2;
    #pragma unroll
    for (int mi = 0; mi < 2; mi++) {
        const int r0 = rbase + mi * 16;
        #pragma unroll
        for (int vt = 0; vt < 8; vt++) {
            *(float2*)&gp[(size_t)r0 * DKH + vt * 8 + cb] =
                make_float2(o[mi][vt][0], o[mi][vt][1]);
            *(float2*)&gp[(size_t)(r0 + 8) * DKH + vt * 8 + cb] =
                make_float2(o[mi][vt][2], o[mi][vt][3]);
        }
        if ((lane & 3) == 0) {
            glp[r0] = l[mi][0];
            glp[r0 + 8] = l[mi][1];
        }
    }
}

// ---------------------------------------------------------------------------
// Kernel 2b: combine split-KV partials -> g_ath (fp16)
// thread idx: row = idx>>4, 4 cols each (c4 = (idx&15)*4)
// ---------------------------------------------------------------------------
__global__ __launch_bounds__(256) void k_comb() {
    const int idx = blockIdx.x * 256 + threadIdx.x;   // NB*NH*LL*16 total
    const int row = idx >> 4;          // [0, 8*4096)
    const int c4 = (idx & 15) * 4;
    const float* p0 = g_part + (size_t)row * DKH;
    const float* p1 = g_part + (size_t)(NB * NH * LL + row) * DKH;
    float4 a = *(const float4*)(p0 + c4);
    float4 b = *(const float4*)(p1 + c4);
    float inv = 1.f / (g_lp[row] + g_lp[NB * NH * LL + row]);
    const int bh = row >> 12, lrow = row & 4095;
    const int bb = bh >> 2, hd = bh & 3;
    uint32_t* dst = (uint32_t*)&g_ath[(size_t)(bb * LL + lrow) * CD + hd * 64 + c4];
    dst[0] = pk_h2((a.x + b.x) * inv, (a.y + b.y) * inv);
    dst[1] = pk_h2((a.z + b.z) * inv, (a.w + b.w) * inv);
}

// ---------------------------------------------------------------------------
// Kernel 3: fc GEMM (single fp16 HMMA) + bias + residual -> g_y fp32.
// ---------------------------------------------------------------------------
__global__ __launch_bounds__(256, 2) void k_fc_mma(const float* __restrict__ fb) {
    extern __shared__ char smg[];
    const uint32_t base = smem_u32(smg);
    const int tid = threadIdx.x, lane = tid & 31, wid = tid >> 5;
    const int m0 = blockIdx.x * 128;
    const int o0 = blockIdx.y * 64;
    const uint32_t laneRow = lane & 15;
    const uint32_t laneCol = ((lane >> 4) & 1) * 16;

    const char* ga = (const char*)(g_ath + (size_t)m0 * CD);
    const char* gb = (const char*)(g_fwh + (size_t)o0 * CD);

    auto pref = [&](int kc) {
        uint32_t st = base + (uint32_t)(kc & 1) * 24576u;
        #pragma unroll
        for (int i = 0; i < 4; i++) {
            int idx = tid + i * 256;
            int r = idx >> 3, c8 = idx & 7;
            uint32_t so = SWZ(r * 128 + c8 * 16);
            size_t go = (size_t)r * 512 + (size_t)kc * 128 + c8 * 16;
            cpa16(st + so, ga + go);
        }
        #pragma unroll
        for (int i = 0; i < 2; i++) {
            int idx = tid + i * 256;
            int r = idx >> 3, c8 = idx & 7;
            uint32_t so = SWZ(r * 128 + c8 * 16);
            size_t go = (size_t)r * 512 + (size_t)kc * 128 + c8 * 16;
            cpa16(st + 16384 + so, gb + go);
        }
    };

    float acc[8][4] = {};
    pref(0); cpa_commit();
    pref(1); cpa_commit();
    #pragma unroll
    for (int kc = 0; kc < 4; kc++) {
        if (kc < 3) cpa_wait<1>(); else cpa_wait<0>();
        __syncthreads();
        uint32_t sb = base + (uint32_t)(kc & 1) * 24576u;
        #pragma unroll
        for (int s = 0; s < 4; s++) {
            uint32_t ah[4];
            uint32_t offA = SWZ((wid * 16 + laneRow) * 128 + s * 32 + laneCol);
            ldsm4(ah, sb + offA);
            #pragma unroll
            for (int nf = 0; nf < 4; nf++) {
                uint32_t offB = SWZ((nf * 16 + laneRow) * 128 + s * 32 + laneCol);
                uint32_t b4[4];
                ldsm4(b4, sb + 16384 + offB);
                mma_f16(acc[2 * nf],     ah, b4[0], b4[2]);
                mma_f16(acc[2 * nf + 1], ah, b4[1], b4[3]);
            }
        }
        __syncthreads();
        if (kc + 2 < 4) { pref(kc + 2); cpa_commit(); }
    }

    const int r = m0 + wid * 16 + (lane >> 2);
    const int cb = (lane & 3) * 2;
    #pragma unroll
    for (int f = 0; f < 8; f++) {
        int c = o0 + f * 8 + cb;
        float b0 = fb[c], b1 = fb[c + 1];
        float2 res0 = *(const float2*)&g_x[(size_t)r * CD + c];
        float2 res1 = *(const float2*)&g_x[(size_t)(r + 8) * CD + c];
        *(float2*)&g_y[(size_t)r * CD + c] =
            make_float2(acc[f][0] + b0 + res0.x, acc[f][1] + b1 + res0.y);
        *(float2*)&g_y[(size_t)(r + 8) * CD + c] =
            make_float2(acc[f][2] + b0 + res1.x, acc[f][3] + b1 + res1.y);
    }
}

// ---------------------------------------------------------------------------
// Kernel 4: LayerNorm over C=256
// ---------------------------------------------------------------------------
__global__ __launch_bounds__(256) void k_ln(const float* __restrict__ gam,
                                            const float* __restrict__ bet,
                                            float* __restrict__ out) {
    const int row = blockIdx.x * 8 + (threadIdx.x >> 5);
    const int lane = threadIdx.x & 31;
    const float* y = g_y + (size_t)row * CD;
    float v[8], s = 0.f, s2 = 0.f;
    #pragma unroll
    for (int k = 0; k < 8; k++) {
        v[k] = y[lane + 32 * k];
        s += v[k];
        s2 += v[k] * v[k];
    }
    #pragma unroll
    for (int off = 16; off; off >>= 1) {
        s  += __shfl_xor_sync(0xffffffffu, s, off);
        s2 += __shfl_xor_sync(0xffffffffu, s2, off);
    }
    const float mu = s * (1.f / CD);
    const float rstd = rsqrtf(s2 * (1.f / CD) - mu * mu + 1e-5f);
    #pragma unroll
    for (int k = 0; k < 8; k++) {
        int c = lane + 32 * k;
        out[(size_t)row * CD + c] = (v[k] - mu) * rstd * gam[c] + bet[c];
    }
}

// ---------------------------------------------------------------------------
extern "C" void kernel_launch(void* const* d_in, const int* in_sizes, int n_in,
                              void* d_out, int out_size) {
    const float* qin = (const float*)d_in[0];
    const float* wq  = (const float*)d_in[1];
    const float* fw  = (const float*)d_in[2];
    const float* fb  = (const float*)d_in[3];
    const float* lg  = (const float*)d_in[4];
    const float* lb  = (const float*)d_in[5];
    float* out = (float*)d_out;

    const int attn_smem = 49152;   // 2 x 16KB ring + 16KB Q
    const int qkv_smem  = 98304;   // 2 x 48KB
    const int fc_smem   = 49152;   // 2 x 24KB
    cudaFuncSetAttribute(k_attn_mma,
                         cudaFuncAttributeMaxDynamicSharedMemorySize, attn_smem);
    cudaFuncSetAttribute(k_qkv_mma,
                         cudaFuncAttributeMaxDynamicSharedMemorySize, qkv_smem);
    cudaFuncSetAttribute(k_fc_mma,
                         cudaFuncAttributeMaxDynamicSharedMemorySize, fc_smem);

    k_prep<<<dim3(LL / 64, CD / 64, NB), 256>>>(qin);
    k_prep_w<<<CD * CD / 256, 256>>>(wq, fw);
    k_qkv_mma<<<dim3(LL / 128, NH, NB), 256, qkv_smem>>>();
    k_attn_mma<<<dim3(LL / 128, NB * NH, 2), 128, attn_smem>>>();
    k_comb<<<NB * NH * LL * 16 / 256, 256>>>();
    k_fc_mma<<<dim3(NB * LL / 128, CD / 64), 256, fc_smem>>>(fb);
    k_ln<<<NB * LL / 8, 256>>>(lg, lb, out);
}